// round 16
// baseline (speedup 1.0000x reference)
#include <cuda_runtime.h>
#include <cuda_bf16.h>
#include <cstdint>

// Fused CrossEntropy + (LUT-remapped) BCE loss — persistent CTAs,
// cp.async.BULK (20KB/tile single-instruction copies) + mbarrier pipeline.
//
// loss = ( sum_i (lse(pred_i) - pred_i[tgt_i]) + 100 * n_mismatch ) / N
// where mismatch_i = [ (argmax(pred_i) in [2,7]) != (tgt_i in [2,7]) ].
//
// vs best (16.4us): balance was neutral -> kernel is paced by DRAM streaming
// at 5.4 TB/s wall. Replace 1280 per-lane 16B cp.async per tile with ONE
// cp.async.bulk of 20480B (+ one 2KB for targets), completing on an mbarrier
// with expect_tx. Fewer/larger DRAM requests, ~1284 fewer instrs per tile
// per CTA, HW-sleep waits. Parity for buffer b at iter idx = (idx>>1)&1.

__device__ double g_acc = 0.0;
__device__ unsigned int g_count = 0u;

#define LOG2E 1.4426950408889634f
#define LN2   0.6931471805599453f

constexpr int THREADS = 256;
constexpr int ROWS_PER_TILE = 2 * THREADS;                 // 512
constexpr int UNITS_PER_TILE = ROWS_PER_TILE * 40 / 16;    // 1280 float4s
constexpr int TILES_PER_CTA = 6;
constexpr int MAX_RESIDENT = 148 * 5;                      // one-wave cap

// Per-row loss minus the v[tgt] gather; caller subtracts v[tgt].
__device__ __forceinline__ float row_loss_nogather(
    float v0, float v1, float v2, float v3, float v4,
    float v5, float v6, float v7, float v8, float v9, int tgt)
{
    const float m01 = fmaxf(v0, v1);
    const float m27 = fmaxf(fmaxf(fmaxf(v2, v3), fmaxf(v4, v5)), fmaxf(v6, v7));
    const float m89 = fmaxf(v8, v9);
    const float m = fmaxf(fmaxf(m01, m27), m89);

    // b_pred without argmax (exact under first-occurrence ties)
    const int bp = (m27 > m01) & (m27 >= m89);
    const int bt = (tgt >= 2) & (tgt <= 7);

    const float mc = m * LOG2E;
    float s;
    s  = exp2f(fmaf(v0, LOG2E, -mc));
    s += exp2f(fmaf(v1, LOG2E, -mc));
    s += exp2f(fmaf(v2, LOG2E, -mc));
    s += exp2f(fmaf(v3, LOG2E, -mc));
    s += exp2f(fmaf(v4, LOG2E, -mc));
    s += exp2f(fmaf(v5, LOG2E, -mc));
    s += exp2f(fmaf(v6, LOG2E, -mc));
    s += exp2f(fmaf(v7, LOG2E, -mc));
    s += exp2f(fmaf(v8, LOG2E, -mc));
    s += exp2f(fmaf(v9, LOG2E, -mc));

    const float lse = fmaf(__log2f(s), LN2, m);

    return lse + ((bp != bt) ? 100.0f : 0.0f);
}

__global__ void __launch_bounds__(THREADS) loss_kernel(
    const float* __restrict__ pred,
    const int* __restrict__ target,
    float* __restrict__ out,
    int n_rows)
{
    __shared__ alignas(16) float4 s_pred[2][UNITS_PER_TILE];  // 2 x 20480 B
    __shared__ alignas(16) int2   s_tgt[2][THREADS];          // 2 x 2048 B
    __shared__ alignas(8) unsigned long long s_mbar[2];
    __shared__ float warp_sums[8];

    const int tid  = threadIdx.x;
    const int lane = tid & 31;
    const int w    = tid >> 5;
    const int G    = gridDim.x;
    const int total_tiles = (n_rows + ROWS_PER_TILE - 1) / ROWS_PER_TILE;
    const int n_pairs = n_rows >> 1;  // full pairs

    const unsigned int full_units =
        (unsigned int)(((long long)n_rows * 40) >> 4);  // whole 16B units
    const float4* __restrict__ gp = reinterpret_cast<const float4*>(pred);
    const int2* __restrict__ gt = reinterpret_cast<const int2*>(target);

    const unsigned int sp_addr0 =
        (unsigned int)__cvta_generic_to_shared(&s_pred[0][0]);
    const unsigned int sp_addr1 =
        (unsigned int)__cvta_generic_to_shared(&s_pred[1][0]);
    const unsigned int st_addr0 =
        (unsigned int)__cvta_generic_to_shared(&s_tgt[0][0]);
    const unsigned int st_addr1 =
        (unsigned int)__cvta_generic_to_shared(&s_tgt[1][0]);
    const unsigned int mb_addr0 =
        (unsigned int)__cvta_generic_to_shared(&s_mbar[0]);
    const unsigned int mb_addr1 =
        (unsigned int)__cvta_generic_to_shared(&s_mbar[1]);

    if (tid == 0) {
        asm volatile("mbarrier.init.shared::cta.b64 [%0], 1;"
                     :: "r"(mb_addr0) : "memory");
        asm volatile("mbarrier.init.shared::cta.b64 [%0], 1;"
                     :: "r"(mb_addr1) : "memory");
        asm volatile("fence.mbarrier_init.release.cluster;" ::: "memory");
    }
    __syncthreads();

    // staged pairs for a tile (rounded down to even so bytes % 16 == 0)
    auto tile_sp = [&](int tile) -> int {
        int sp = n_pairs - tile * THREADS;
        sp = (sp < 0) ? 0 : ((sp > THREADS) ? THREADS : sp);
        return sp & ~1;
    };

    // tid==0 only: arm mbarrier and issue bulk copies for 'tile' into 'buf'
    auto stage = [&](int buf, int tile) {
        const unsigned int ubase =
            (unsigned int)tile * (unsigned int)UNITS_PER_TILE;
        unsigned int units = (full_units > ubase) ? (full_units - ubase) : 0u;
        if (units > (unsigned int)UNITS_PER_TILE)
            units = (unsigned int)UNITS_PER_TILE;
        const unsigned int pb = units * 16u;
        const unsigned int tb = (unsigned int)tile_sp(tile) * 8u;
        const unsigned int mb = buf ? mb_addr1 : mb_addr0;
        asm volatile("mbarrier.arrive.expect_tx.shared::cta.b64 _, [%0], %1;"
                     :: "r"(mb), "r"(pb + tb) : "memory");
        if (pb) {
            asm volatile(
                "cp.async.bulk.shared::cta.global.mbarrier::complete_tx::bytes"
                " [%0], [%1], %2, [%3];"
                :: "r"(buf ? sp_addr1 : sp_addr0), "l"(gp + ubase),
                   "r"(pb), "r"(mb) : "memory");
        }
        if (tb) {
            asm volatile(
                "cp.async.bulk.shared::cta.global.mbarrier::complete_tx::bytes"
                " [%0], [%1], %2, [%3];"
                :: "r"(buf ? st_addr1 : st_addr0),
                   "l"(gt + (size_t)tile * THREADS),
                   "r"(tb), "r"(mb) : "memory");
        }
    };

    // ---- prologue: stage up to 2 tiles ----
    const int tile0 = blockIdx.x;
    if (tid == 0) {
        stage(0, tile0);
        if (tile0 + G < total_tiles) stage(1, tile0 + G);
    }

    // ---- steady state ----
    float local = 0.0f;
    int idx = 0;
    for (int tile = tile0; tile < total_tiles; tile += G, idx++) {
        const int buf = idx & 1;
        const unsigned int par = (unsigned int)((idx >> 1) & 1);
        const unsigned int mb = buf ? mb_addr1 : mb_addr0;

        // wait for tile data (HW-sleep try_wait loop)
        {
            unsigned int done = 0;
            while (!done) {
                asm volatile(
                    "{\n\t.reg .pred p;\n\t"
                    "mbarrier.try_wait.parity.acquire.cta.shared::cta.b64 "
                    "p, [%1], %2, 0x989680;\n\t"
                    "selp.b32 %0, 1, 0, p;\n\t}"
                    : "=r"(done) : "r"(mb), "r"(par) : "memory");
            }
        }

        const int pair = tile * THREADS + tid;
        const int r0 = 2 * pair;
        const int sp_count = tile_sp(tile);
        if (r0 + 1 < n_rows) {
            const float4* __restrict__ sp = &s_pred[buf][0] + tid * 5;
            const float4 q0 = sp[0];
            const float4 q1 = sp[1];
            const float4 q2 = sp[2];
            const float4 q3 = sp[3];
            const float4 q4 = sp[4];
            int2 tt;
            if (tid < sp_count) tt = s_tgt[buf][tid];
            else                tt = gt[pair];  // un-staged odd straggler
            const int t0 = min(max(tt.x, 0), 9);
            const int t1 = min(max(tt.y, 0), 9);

            const float* __restrict__ row0 =
                reinterpret_cast<const float*>(sp);
            const float vt0 = row0[t0];
            const float vt1 = row0[10 + t1];

            local += row_loss_nogather(q0.x, q0.y, q0.z, q0.w,
                                       q1.x, q1.y, q1.z, q1.w,
                                       q2.x, q2.y, t0) - vt0
                   + row_loss_nogather(q2.z, q2.w,
                                       q3.x, q3.y, q3.z, q3.w,
                                       q4.x, q4.y, q4.z, q4.w, t1) - vt1;
        } else if (r0 < n_rows) {
            // odd-N single tail row: read directly from global
            const float2* __restrict__ p =
                reinterpret_cast<const float2*>(pred + (size_t)r0 * 10);
            const float2 a0 = p[0];
            const float2 a1 = p[1];
            const float2 a2 = p[2];
            const float2 a3 = p[3];
            const float2 a4 = p[4];
            float v[10] = {a0.x, a0.y, a1.x, a1.y, a2.x,
                           a2.y, a3.x, a3.y, a4.x, a4.y};
            int t0 = min(max(target[r0], 0), 9);
            float vt = v[0];
#pragma unroll
            for (int j = 1; j < 10; j++) vt = (t0 == j) ? v[j] : vt;
            local += row_loss_nogather(v[0], v[1], v[2], v[3], v[4],
                                       v[5], v[6], v[7], v[8], v[9], t0) - vt;
        }

        __syncthreads();  // all threads done reading buf before re-staging

        const int pft = tile + 2 * G;
        if (tid == 0 && pft < total_tiles) stage(buf, pft);
    }

    // ---- block reduction: warp shuffle -> shared -> one double red ----
#pragma unroll
    for (int off = 16; off > 0; off >>= 1)
        local += __shfl_down_sync(0xFFFFFFFFu, local, off);

    if (lane == 0) warp_sums[w] = local;
    __syncthreads();

    __shared__ bool is_last;
    if (w == 0) {
        float blk = (lane < 8) ? warp_sums[lane] : 0.0f;
#pragma unroll
        for (int off = 4; off > 0; off >>= 1)
            blk += __shfl_down_sync(0xFFFFFFFFu, blk, off);
        if (lane == 0) {
            const double dblk = (double)blk;
            asm volatile("red.release.gpu.global.add.f64 [%0], %1;"
                         :: "l"(&g_acc), "d"(dblk) : "memory");
            unsigned int done;
            unsigned int one = 1u;
            asm volatile("atom.acq_rel.gpu.global.add.u32 %0, [%1], %2;"
                         : "=r"(done) : "l"(&g_count), "r"(one) : "memory");
            is_last = (done == gridDim.x - 1u);
        }
    }
    __syncthreads();

    // Last block finalizes: write output, reset state for next replay.
    if (is_last && tid == 0) {
        double acc;
        asm volatile("ld.acquire.gpu.global.f64 %0, [%1];"
                     : "=d"(acc) : "l"(&g_acc) : "memory");
        out[0] = (float)(acc / (double)n_rows);
        g_acc = 0.0;
        g_count = 0u;
    }
}

extern "C" void kernel_launch(void* const* d_in, const int* in_sizes, int n_in,
                              void* d_out, int out_size) {
    const float* pred   = (const float*)d_in[0];
    const int*   target = (const int*)d_in[1];
    float*       out    = (float*)d_out;

    const int n_rows = in_sizes[1];  // target element count = N
    const int total_tiles = (n_rows + ROWS_PER_TILE - 1) / ROWS_PER_TILE;

    int blocks = (total_tiles + TILES_PER_CTA - 1) / TILES_PER_CTA;
    if (blocks > MAX_RESIDENT) blocks = MAX_RESIDENT;
    if (blocks < 1) blocks = 1;

    loss_kernel<<<blocks, THREADS>>>(pred, target, out, n_rows);
}